// round 15
// baseline (speedup 1.0000x reference)
#include <cuda_runtime.h>
#include <cuda_fp16.h>
#include <cstdint>

#define TOKENS   64
#define NFEAT    8192
#define KFEAT    8192

#define CTA_N     128
#define ITER_C    64                    // codes per iteration
#define PITCH     72                    // halves per smem row (144B, conflict-free)
#define NSTAGE    3
#define NSLICE    5

#define B_STAGE   (CTA_N * PITCH * 2)   // 18432 B
#define A_STAGE   (TOKENS * PITCH * 2)  // 9216 B
#define A_BASE    (NSTAGE * B_STAGE)    // 55296
#define SMEM_TOTAL (A_BASE + NSTAGE * A_STAGE)  // 82944

// scratch
__device__ __align__(16) __half g_x16[TOKENS * KFEAT];              // 1MB fp16 x
__device__ float g_sumx[TOKENS];
__device__ __align__(16) float g_part[NSLICE][TOKENS * NFEAT];      // 10MB

// ---------------------------------------------------------------------------
// Prep: plain fp16 convert + token sums.
// ---------------------------------------------------------------------------
__global__ __launch_bounds__(512) void prep_kernel(const float* __restrict__ x) {
    __shared__ float s_w[16];
    const int t = blockIdx.x, tid = threadIdx.x;
    const float4* xr = reinterpret_cast<const float4*>(x + (size_t)t * KFEAT);
    uint4* dst = reinterpret_cast<uint4*>(g_x16 + (size_t)t * KFEAT);
    float sm = 0.f;
    uint4 o0, o1;
    {
        float4 f = xr[tid * 4 + 0];
        __half2 h0 = __floats2half2_rn(f.x, f.y), h1 = __floats2half2_rn(f.z, f.w);
        sm += (__low2float(h0) + __high2float(h0)) + (__low2float(h1) + __high2float(h1));
        o0.x = *(uint32_t*)&h0; o0.y = *(uint32_t*)&h1;
        f = xr[tid * 4 + 1];
        h0 = __floats2half2_rn(f.x, f.y); h1 = __floats2half2_rn(f.z, f.w);
        sm += (__low2float(h0) + __high2float(h0)) + (__low2float(h1) + __high2float(h1));
        o0.z = *(uint32_t*)&h0; o0.w = *(uint32_t*)&h1;
        f = xr[tid * 4 + 2];
        h0 = __floats2half2_rn(f.x, f.y); h1 = __floats2half2_rn(f.z, f.w);
        sm += (__low2float(h0) + __high2float(h0)) + (__low2float(h1) + __high2float(h1));
        o1.x = *(uint32_t*)&h0; o1.y = *(uint32_t*)&h1;
        f = xr[tid * 4 + 3];
        h0 = __floats2half2_rn(f.x, f.y); h1 = __floats2half2_rn(f.z, f.w);
        sm += (__low2float(h0) + __high2float(h0)) + (__low2float(h1) + __high2float(h1));
        o1.z = *(uint32_t*)&h0; o1.w = *(uint32_t*)&h1;
    }
    dst[tid * 2] = o0; dst[tid * 2 + 1] = o1;
#pragma unroll
    for (int o = 16; o > 0; o >>= 1) sm += __shfl_xor_sync(0xFFFFFFFFu, sm, o);
    if ((tid & 31) == 0) s_w[tid >> 5] = sm;
    __syncthreads();
    if (tid < 32) {
        float r = (tid < 16) ? s_w[tid] : 0.f;
#pragma unroll
        for (int o = 8; o > 0; o >>= 1) r += __shfl_xor_sync(0xFFFFFFFFu, r, o);
        if (tid == 0) g_sumx[t] = r;
    }
}

// ---------------------------------------------------------------------------
__device__ __forceinline__ void cpa16(uint32_t dst, const void* src) {
    asm volatile("cp.async.ca.shared.global [%0], [%1], 16;\n" :: "r"(dst), "l"(src));
}
#define CP_COMMIT() asm volatile("cp.async.commit_group;\n" ::: "memory")
#define CP_WAIT1()  asm volatile("cp.async.wait_group 1;\n" ::: "memory")

__device__ __forceinline__ int4 ldg_cs(const int* p) {
    int4 v;
    asm volatile("ld.global.cs.v4.b32 {%0,%1,%2,%3}, [%4];"
        : "=r"(v.x), "=r"(v.y), "=r"(v.z), "=r"(v.w) : "l"(p));
    return v;
}
// [a.b0, 0, b.b0, 0] -> half2 {ca*2^-24, cb*2^-24} (exact), one PRMT.
__device__ __forceinline__ uint32_t pack2(uint32_t a, uint32_t b) {
    uint32_t r;
    asm("prmt.b32 %0, %1, %2, 0x5410;" : "=r"(r) : "r"(a), "r"(b));
    return r;
}
__device__ __forceinline__ void mma16816(float* d, const uint32_t* a, uint32_t b0, uint32_t b1) {
    asm volatile(
        "mma.sync.aligned.m16n8k16.row.col.f32.f16.f16.f32 "
        "{%0,%1,%2,%3},{%4,%5,%6,%7},{%8,%9},{%0,%1,%2,%3};"
        : "+f"(d[0]), "+f"(d[1]), "+f"(d[2]), "+f"(d[3])
        : "r"(a[0]), "r"(a[1]), "r"(a[2]), "r"(a[3]), "r"(b0), "r"(b1));
}
#define LDSM4(R0, R1, R2, R3, addr)                                            \
    asm volatile("ldmatrix.sync.aligned.m8n8.x4.shared.b16 {%0,%1,%2,%3}, [%4];" \
        : "=r"(R0), "=r"(R1), "=r"(R2), "=r"(R3) : "r"(addr))

// ---------------------------------------------------------------------------
// GEMM: 296 balanced segments; 2M x 4N warp tiling (min smem traffic).
// ---------------------------------------------------------------------------
__global__ __launch_bounds__(256, 2) void gemm_kernel(const int* __restrict__ q) {
    extern __shared__ __align__(16) uint8_t smem[];
    const int tid  = threadIdx.x;
    const int warp = tid >> 5;
    const int lane = tid & 31;
    const uint32_t sbase = (uint32_t)__cvta_generic_to_shared(smem);

    // ---- balanced segment schedule (bid & bid+148 co-reside per LUT) ----
    const int bid = blockIdx.x;          // 0..295
    const int s = bid % 148, w = bid / 148;
    int tile, start, len, ord;
    if (s < 96 && w == 0) {              // 32-iter segments, tiles 0..23
        tile = s >> 2; ord = s & 3; start = ord * 32; len = 32;
    } else if (s < 80) {                 // w==1: 25-iter segments, tiles 24..63
        tile = 24 + (s >> 1); ord = 3 + (s & 1); start = (s & 1) ? 103 : 78; len = 25;
    } else {                             // 26-iter segments, tiles 24..63
        int k = (s < 96) ? (s - 80) : (16 + 2 * (s - 96) + w);
        tile = 24 + k / 3; ord = k % 3; start = ord * 26; len = 26;
    }

    const int blockN = tile * CTA_N;
    const int kb = start * ITER_C;

    // ---- B producer mapping ----
    const int crow = tid >> 4;
    const int cc   = tid & 15;
    const int* pB = q + (size_t)(blockN + crow) * KFEAT + kb + cc * 4;
    const uint32_t sts_off = (uint32_t)(crow * (PITCH * 2) + cc * 8);

    // ---- A producer mapping ----
    const int arow = tid >> 2;
    const int aseg = tid & 3;
    const __half* asrc = g_x16 + (size_t)arow * KFEAT + kb + aseg * 8;
    const uint32_t adst = (uint32_t)(arow * PITCH + aseg * 8) * 2;

#define LDG_RAW(it) do {                                                        \
    _Pragma("unroll")                                                           \
    for (int j = 0; j < 8; j++)                                                 \
        raw[j] = ldg_cs(pB + (size_t)j * 16 * KFEAT + (it) * ITER_C);           \
} while (0)

#define STS_RAW(st_) do {                                                       \
    _Pragma("unroll")                                                           \
    for (int j = 0; j < 8; j++) {                                               \
        uint32_t p0 = pack2((uint32_t)raw[j].x, (uint32_t)raw[j].y);            \
        uint32_t p1 = pack2((uint32_t)raw[j].z, (uint32_t)raw[j].w);            \
        asm volatile("st.shared.v2.b32 [%0], {%1,%2};"                          \
            :: "r"((st_) + sts_off + (uint32_t)(j * 16 * PITCH * 2)),           \
               "r"(p0), "r"(p1) : "memory");                                    \
    }                                                                           \
} while (0)

    int4 raw[8];
    LDG_RAW(0);
    STS_RAW(sbase);
    LDG_RAW(1);
#pragma unroll
    for (int i = 0; i < 2; i++) {
        cpa16(sbase + A_BASE + i * A_STAGE + adst, asrc + (size_t)i * ITER_C);
        cpa16(sbase + A_BASE + i * A_STAGE + adst + 64, asrc + (size_t)i * ITER_C + 32);
        CP_COMMIT();
    }

    // ---- consumer: 2M x 4N warp tiling ----
    const int mw = warp & 1;             // 0..1 : token half (32 rows)
    const int nw = warp >> 1;            // 0..3 : channel group (32 channels)

    float acc[2][4][4];
#pragma unroll
    for (int mi = 0; mi < 2; mi++)
#pragma unroll
        for (int nf = 0; nf < 4; nf++)
#pragma unroll
            for (int j = 0; j < 4; j++) acc[mi][nf][j] = 0.f;

    const int rl = lane & 15;
    const int kh = (lane >> 4) * 8;
    const int bq = lane >> 3;
    const uint32_t brow0 =
        (uint32_t)((nw * 32 + (bq >> 1) * 8 + (lane & 7)) * (PITCH * 2) + (bq & 1) * 16);
    const uint32_t brow1 = brow0 + (uint32_t)(16 * PITCH * 2);

    int sb = 0, sn = 1;
    for (int i = 0; i < len; i++) {
        CP_WAIT1();
        __syncthreads();

        int s2 = sn + 1; if (s2 == NSTAGE) s2 = 0;
        if (i + 2 < len) {
            const __half* sA2 = asrc + (size_t)(i + 2) * ITER_C;
            cpa16(sbase + A_BASE + s2 * A_STAGE + adst, sA2);
            cpa16(sbase + A_BASE + s2 * A_STAGE + adst + 64, sA2 + 32);
        }
        CP_COMMIT();

        if (i + 1 < len) STS_RAW(sbase + (uint32_t)sn * B_STAGE);
        if (i + 2 < len) LDG_RAW(i + 2);

        const uint32_t bstg = sbase + (uint32_t)sb * B_STAGE;
        const uint32_t astg = sbase + A_BASE + (uint32_t)sb * A_STAGE;

#pragma unroll
        for (int ss = 0; ss < 4; ss++) {
            uint32_t b0[4], b1[4];       // [nf]: b0 pairs via two LDSM4
            LDSM4(b0[0], b0[1], b0[2], b0[3], bstg + brow0 + (uint32_t)(ss * 32));
            LDSM4(b1[0], b1[1], b1[2], b1[3], bstg + brow1 + (uint32_t)(ss * 32));
            uint32_t a[2][4];
#pragma unroll
            for (int mi = 0; mi < 2; mi++) {
                uint32_t addr = astg +
                    (uint32_t)((mw * 32 + mi * 16 + rl) * PITCH + ss * 16 + kh) * 2;
                LDSM4(a[mi][0], a[mi][1], a[mi][2], a[mi][3], addr);
            }
#pragma unroll
            for (int mi = 0; mi < 2; mi++) {
                mma16816(acc[mi][0], a[mi], b0[0], b0[1]);
                mma16816(acc[mi][1], a[mi], b0[2], b0[3]);
                mma16816(acc[mi][2], a[mi], b1[0], b1[1]);
                mma16816(acc[mi][3], a[mi], b1[2], b1[3]);
            }
        }
        sb = sn; sn = s2;
    }

    // epilogue: raw partial dots into slice `ord`
    float* pp = &g_part[ord][0];
    const int kc2 = (lane & 3) * 2;
#pragma unroll
    for (int mi = 0; mi < 2; mi++)
#pragma unroll
        for (int nf = 0; nf < 4; nf++) {
            int col = blockN + nw * 32 + nf * 8 + kc2;
            int t0  = mw * 32 + mi * 16 + (lane >> 2);
            *reinterpret_cast<float2*>(&pp[(size_t)t0 * NFEAT + col]) =
                make_float2(acc[mi][nf][0], acc[mi][nf][1]);
            *reinterpret_cast<float2*>(&pp[(size_t)(t0 + 8) * NFEAT + col]) =
                make_float2(acc[mi][nf][2], acc[mi][nf][3]);
        }
#undef LDG_RAW
#undef STS_RAW
}

// ---------------------------------------------------------------------------
// Reduce: y = s * (2^24 * sum_slices - zp * sumx_t) + bias
// Tiles 0..23 have 4 slices; tiles 24..63 have 5.
// ---------------------------------------------------------------------------
__global__ void reduce_kernel(const float* __restrict__ scales,
                              const int* __restrict__ zp,
                              const float* __restrict__ bias,
                              float* __restrict__ out) {
    int i = blockIdx.x * blockDim.x + threadIdx.x;     // float4 units
    int col4 = i & (NFEAT / 4 - 1);
    int t    = i >> 11;
    float4 a = reinterpret_cast<const float4*>(g_part[0])[i];
    float4 b = reinterpret_cast<const float4*>(g_part[1])[i];
    float4 c = reinterpret_cast<const float4*>(g_part[2])[i];
    float4 d = reinterpret_cast<const float4*>(g_part[3])[i];
    float4 e = make_float4(0.f, 0.f, 0.f, 0.f);
    if (col4 >= 24 * 32) e = reinterpret_cast<const float4*>(g_part[4])[i];
    float4 sc = reinterpret_cast<const float4*>(scales)[col4];
    float4 bi = reinterpret_cast<const float4*>(bias)[col4];
    int4   zi = reinterpret_cast<const int4*>(zp)[col4];
    float sx = g_sumx[t];
    const float SC = 16777216.0f;  // 2^24
    float4 r;
    r.x = bi.x + sc.x * (SC * (((a.x + b.x) + (c.x + d.x)) + e.x) - (float)zi.x * sx);
    r.y = bi.y + sc.y * (SC * (((a.y + b.y) + (c.y + d.y)) + e.y) - (float)zi.y * sx);
    r.z = bi.z + sc.z * (SC * (((a.z + b.z) + (c.z + d.z)) + e.z) - (float)zi.z * sx);
    r.w = bi.w + sc.w * (SC * (((a.w + b.w) + (c.w + d.w)) + e.w) - (float)zi.w * sx);
    reinterpret_cast<float4*>(out)[i] = r;
}

// ---------------------------------------------------------------------------
extern "C" void kernel_launch(void* const* d_in, const int* in_sizes, int n_in,
                              void* d_out, int out_size) {
    const float* x    = (const float*)d_in[0];
    const int*   qw   = (const int*)d_in[1];
    const float* sc   = (const float*)d_in[2];
    const int*   zp   = (const int*)d_in[3];
    const float* bias = (const float*)d_in[4];
    float*       out  = (float*)d_out;
    (void)in_sizes; (void)n_in; (void)out_size;

    cudaFuncSetAttribute(gemm_kernel, cudaFuncAttributeMaxDynamicSharedMemorySize, SMEM_TOTAL);

    prep_kernel<<<TOKENS, 512>>>(x);
    gemm_kernel<<<296, 256, SMEM_TOTAL>>>(qw);
    reduce_kernel<<<(TOKENS * NFEAT / 4) / 256, 256>>>(sc, zp, bias, out);
}

// round 17
// speedup vs baseline: 1.0029x; 1.0029x over previous
#include <cuda_runtime.h>
#include <cuda_fp16.h>
#include <cstdint>

#define TOKENS   64
#define NFEAT    8192
#define KFEAT    8192

#define CTA_N     128
#define ITER_C    64                    // codes per iteration
#define PITCH     72                    // halves per smem row (144B)
#define NSTAGE    3
#define NSLICE    5

#define B_STAGE   (CTA_N * PITCH * 2)   // 18432 B
#define A_STAGE   (TOKENS * PITCH * 2)  // 9216 B
#define A_BASE    (NSTAGE * B_STAGE)    // 55296
#define SMEM_TOTAL (A_BASE + NSTAGE * A_STAGE)  // 82944

// scratch
__device__ __align__(16) float g_part[NSLICE][TOKENS * NFEAT];      // 10MB

// ---------------------------------------------------------------------------
__device__ __forceinline__ int4 ldg_cs(const int* p) {
    int4 v;
    asm volatile("ld.global.cs.v4.b32 {%0,%1,%2,%3}, [%4];"
        : "=r"(v.x), "=r"(v.y), "=r"(v.z), "=r"(v.w) : "l"(p));
    return v;
}
// [a.b0, 0, b.b0, 0] -> half2 {ca*2^-24, cb*2^-24} (exact), one PRMT.
__device__ __forceinline__ uint32_t pack2(uint32_t a, uint32_t b) {
    uint32_t r;
    asm("prmt.b32 %0, %1, %2, 0x5410;" : "=r"(r) : "r"(a), "r"(b));
    return r;
}
__device__ __forceinline__ void mma16816(float* d, const uint32_t* a, uint32_t b0, uint32_t b1) {
    asm volatile(
        "mma.sync.aligned.m16n8k16.row.col.f32.f16.f16.f32 "
        "{%0,%1,%2,%3},{%4,%5,%6,%7},{%8,%9},{%0,%1,%2,%3};"
        : "+f"(d[0]), "+f"(d[1]), "+f"(d[2]), "+f"(d[3])
        : "r"(a[0]), "r"(a[1]), "r"(a[2]), "r"(a[3]), "r"(b0), "r"(b1));
}
#define LDSM4(R0, R1, R2, R3, addr)                                            \
    asm volatile("ldmatrix.sync.aligned.m8n8.x4.shared.b16 {%0,%1,%2,%3}, [%4];" \
        : "=r"(R0), "=r"(R1), "=r"(R2), "=r"(R3) : "r"(addr))

// ---------------------------------------------------------------------------
// GEMM: 296 balanced segments; B: LDG->PRMT->STS; A: LDG(fp32 x)->cvt->STS.
// ---------------------------------------------------------------------------
__global__ __launch_bounds__(256, 2) void gemm_kernel(const int* __restrict__ q,
                                                      const float* __restrict__ x) {
    extern __shared__ __align__(16) uint8_t smem[];
    const int tid  = threadIdx.x;
    const int warp = tid >> 5;
    const int lane = tid & 31;
    const uint32_t sbase = (uint32_t)__cvta_generic_to_shared(smem);

    // ---- balanced segment schedule ----
    const int bid = blockIdx.x;          // 0..295
    const int s = bid % 148, w = bid / 148;
    int tile, start, len, ord;
    if (s < 96 && w == 0) {
        tile = s >> 2; ord = s & 3; start = ord * 32; len = 32;
    } else if (s < 80) {
        tile = 24 + (s >> 1); ord = 3 + (s & 1); start = (s & 1) ? 103 : 78; len = 25;
    } else {
        int k = (s < 96) ? (s - 80) : (16 + 2 * (s - 96) + w);
        tile = 24 + k / 3; ord = k % 3; start = ord * 26; len = 26;
    }

    const int blockN = tile * CTA_N;
    const int kb = start * ITER_C;

    // ---- B producer mapping ----
    const int crow = tid >> 4;
    const int cc   = tid & 15;
    const int* pB = q + (size_t)(blockN + crow) * KFEAT + kb + cc * 4;
    const uint32_t sts_off = (uint32_t)(crow * (PITCH * 2) + cc * 8);

    // ---- A producer mapping ----
    const int arow = tid >> 4;           // 0..15
    const int ac   = tid & 15;           // 16B fp32 chunk
    const float* pX = x + (size_t)arow * KFEAT + kb + ac * 4;
    const uint32_t ast_off = (uint32_t)(arow * PITCH + ac * 4) * 2;

#define BLDG(it) do {                                                           \
    _Pragma("unroll")                                                           \
    for (int j = 0; j < 8; j++)                                                 \
        braw[j] = ldg_cs(pB + (size_t)j * 16 * KFEAT + (it) * ITER_C);          \
} while (0)

#define BSTS(st_) do {                                                          \
    _Pragma("unroll")                                                           \
    for (int j = 0; j < 8; j++) {                                               \
        uint32_t p0 = pack2((uint32_t)braw[j].x, (uint32_t)braw[j].y);          \
        uint32_t p1 = pack2((uint32_t)braw[j].z, (uint32_t)braw[j].w);          \
        asm volatile("st.shared.v2.b32 [%0], {%1,%2};"                          \
            :: "r"((st_) + sts_off + (uint32_t)(j * 16 * PITCH * 2)),           \
               "r"(p0), "r"(p1) : "memory");                                    \
    }                                                                           \
} while (0)

#define XLDG(it) do {                                                           \
    _Pragma("unroll")                                                           \
    for (int j = 0; j < 4; j++)                                                 \
        xraw[j] = *reinterpret_cast<const float4*>(                             \
            pX + (size_t)j * 16 * KFEAT + (it) * ITER_C);                       \
} while (0)

#define XSTS(ast_) do {                                                         \
    _Pragma("unroll")                                                           \
    for (int j = 0; j < 4; j++) {                                               \
        __half2 h0 = __floats2half2_rn(xraw[j].x, xraw[j].y);                   \
        __half2 h1 = __floats2half2_rn(xraw[j].z, xraw[j].w);                   \
        asm volatile("st.shared.v2.b32 [%0], {%1,%2};"                          \
            :: "r"((ast_) + ast_off + (uint32_t)(j * 16 * PITCH * 2)),          \
               "r"(*(uint32_t*)&h0), "r"(*(uint32_t*)&h1) : "memory");          \
    }                                                                           \
} while (0)

    int4   braw[8];
    float4 xraw[4];

    BLDG(0); XLDG(0);
    BSTS(sbase); XSTS(sbase + A_BASE);
    BLDG(1); XLDG(1);

    // ---- consumer: 2M x 4N warp tiling ----
    const int mw = warp & 1;
    const int nw = warp >> 1;

    float acc[2][4][4];
#pragma unroll
    for (int mi = 0; mi < 2; mi++)
#pragma unroll
        for (int nf = 0; nf < 4; nf++)
#pragma unroll
            for (int j = 0; j < 4; j++) acc[mi][nf][j] = 0.f;

    const int rl = lane & 15;
    const int kh = (lane >> 4) * 8;
    const int bq = lane >> 3;
    const uint32_t brow0 =
        (uint32_t)((nw * 32 + (bq >> 1) * 8 + (lane & 7)) * (PITCH * 2) + (bq & 1) * 16);
    const uint32_t brow1 = brow0 + (uint32_t)(16 * PITCH * 2);

    int sb = 0, sn = 1;
    for (int i = 0; i < len; i++) {
        __syncthreads();

        int s2 = sn + 1; if (s2 == NSTAGE) s2 = 0;
        if (i + 1 < len) {
            BSTS(sbase + (uint32_t)sn * B_STAGE);
            XSTS(sbase + A_BASE + (uint32_t)sn * A_STAGE);
        }
        if (i + 2 < len) { BLDG(i + 2); XLDG(i + 2); }

        const uint32_t bstg = sbase + (uint32_t)sb * B_STAGE;
        const uint32_t astg = sbase + A_BASE + (uint32_t)sb * A_STAGE;

#pragma unroll
        for (int ss = 0; ss < 4; ss++) {
            uint32_t b0[4], b1[4];
            LDSM4(b0[0], b0[1], b0[2], b0[3], bstg + brow0 + (uint32_t)(ss * 32));
            LDSM4(b1[0], b1[1], b1[2], b1[3], bstg + brow1 + (uint32_t)(ss * 32));
            uint32_t a[2][4];
#pragma unroll
            for (int mi = 0; mi < 2; mi++) {
                uint32_t addr = astg +
                    (uint32_t)((mw * 32 + mi * 16 + rl) * PITCH + ss * 16 + kh) * 2;
                LDSM4(a[mi][0], a[mi][1], a[mi][2], a[mi][3], addr);
            }
#pragma unroll
            for (int mi = 0; mi < 2; mi++) {
                mma16816(acc[mi][0], a[mi], b0[0], b0[1]);
                mma16816(acc[mi][1], a[mi], b0[2], b0[3]);
                mma16816(acc[mi][2], a[mi], b1[0], b1[1]);
                mma16816(acc[mi][3], a[mi], b1[2], b1[3]);
            }
        }
        sb = sn; sn = s2;
    }

    // epilogue: raw partial dots into slice `ord`
    float* pp = &g_part[ord][0];
    const int kc2 = (lane & 3) * 2;
#pragma unroll
    for (int mi = 0; mi < 2; mi++)
#pragma unroll
        for (int nf = 0; nf < 4; nf++) {
            int col = blockN + nw * 32 + nf * 8 + kc2;
            int t0  = mw * 32 + mi * 16 + (lane >> 2);
            *reinterpret_cast<float2*>(&pp[(size_t)t0 * NFEAT + col]) =
                make_float2(acc[mi][nf][0], acc[mi][nf][1]);
            *reinterpret_cast<float2*>(&pp[(size_t)(t0 + 8) * NFEAT + col]) =
                make_float2(acc[mi][nf][2], acc[mi][nf][3]);
        }
#undef BLDG
#undef BSTS
#undef XLDG
#undef XSTS
}

// ---------------------------------------------------------------------------
// Reduce: one block per token. Phase 1: sx = sum(x[t]) in fp32.
// Phase 2: y = s * (2^24 * sum_slices - zp * sx) + bias.
// ---------------------------------------------------------------------------
__global__ __launch_bounds__(512) void reduce_kernel(
    const float* __restrict__ x, const float* __restrict__ scales,
    const int* __restrict__ zp, const float* __restrict__ bias,
    float* __restrict__ out) {
    __shared__ float s_w[16];
    __shared__ float s_sx;
    const int t = blockIdx.x, tid = threadIdx.x;

    const float4* xr = reinterpret_cast<const float4*>(x + (size_t)t * KFEAT);
    float sm = 0.f;
#pragma unroll
    for (int i = 0; i < 4; i++) {
        float4 f = xr[tid + 512 * i];
        sm += (f.x + f.y) + (f.z + f.w);
    }
#pragma unroll
    for (int o = 16; o > 0; o >>= 1) sm += __shfl_xor_sync(0xFFFFFFFFu, sm, o);
    if ((tid & 31) == 0) s_w[tid >> 5] = sm;
    __syncthreads();
    if (tid < 32) {
        float r = (tid < 16) ? s_w[tid] : 0.f;
#pragma unroll
        for (int o = 8; o > 0; o >>= 1) r += __shfl_xor_sync(0xFFFFFFFFu, r, o);
        if (tid == 0) s_sx = r;
    }
    __syncthreads();
    const float sx = s_sx;

    const float SC = 16777216.0f;  // 2^24
#pragma unroll
    for (int u = 0; u < 4; u++) {
        int col4 = tid + u * 512;
        size_t i = (size_t)t * (NFEAT / 4) + col4;
        float4 a = reinterpret_cast<const float4*>(g_part[0])[i];
        float4 b = reinterpret_cast<const float4*>(g_part[1])[i];
        float4 c = reinterpret_cast<const float4*>(g_part[2])[i];
        float4 d = reinterpret_cast<const float4*>(g_part[3])[i];
        float4 e = make_float4(0.f, 0.f, 0.f, 0.f);
        if (col4 >= 24 * 32) e = reinterpret_cast<const float4*>(g_part[4])[i];
        float4 sc = reinterpret_cast<const float4*>(scales)[col4];
        float4 bi = reinterpret_cast<const float4*>(bias)[col4];
        int4   zi = reinterpret_cast<const int4*>(zp)[col4];
        float4 r;
        r.x = bi.x + sc.x * (SC * (((a.x + b.x) + (c.x + d.x)) + e.x) - (float)zi.x * sx);
        r.y = bi.y + sc.y * (SC * (((a.y + b.y) + (c.y + d.y)) + e.y) - (float)zi.y * sx);
        r.z = bi.z + sc.z * (SC * (((a.z + b.z) + (c.z + d.z)) + e.z) - (float)zi.z * sx);
        r.w = bi.w + sc.w * (SC * (((a.w + b.w) + (c.w + d.w)) + e.w) - (float)zi.w * sx);
        reinterpret_cast<float4*>(out)[i] = r;
    }
}

// ---------------------------------------------------------------------------
extern "C" void kernel_launch(void* const* d_in, const int* in_sizes, int n_in,
                              void* d_out, int out_size) {
    const float* x    = (const float*)d_in[0];
    const int*   qw   = (const int*)d_in[1];
    const float* sc   = (const float*)d_in[2];
    const int*   zp   = (const int*)d_in[3];
    const float* bias = (const float*)d_in[4];
    float*       out  = (float*)d_out;
    (void)in_sizes; (void)n_in; (void)out_size;

    cudaFuncSetAttribute(gemm_kernel, cudaFuncAttributeMaxDynamicSharedMemorySize, SMEM_TOTAL);

    gemm_kernel<<<296, 256, SMEM_TOTAL>>>(qw, x);
    reduce_kernel<<<TOKENS, 512>>>(x, sc, zp, bias, out);
}